// round 1
// baseline (speedup 1.0000x reference)
#include <cuda_runtime.h>
#include <cuda_bf16.h>

#define NB  8
#define NN  1024
#define NC  64
#define KP1 5
#define RPB 4

// Scratch (no allocations allowed)
__device__ __align__(16) float g_srcR[NB*NN];
__device__ __align__(16) float g_srcI[NB*NN];
__device__ __align__(16) float g_dstR[NB*NN];
__device__ __align__(16) float g_dstI[NB*NN];
__device__ __align__(16) float g_rden[NB*NN];

// ---------------------------------------------------------------------------
// Kernel 1: per-row complex projections. One warp per (b,n) row.
// src_r/src_i get ab_real/ab_imag baked in (s = src + dst + ab).
// ---------------------------------------------------------------------------
__global__ void k_src(const float* __restrict__ Xr, const float* __restrict__ Xi,
                      const float* __restrict__ awr, const float* __restrict__ awi,
                      const float* __restrict__ abr, const float* __restrict__ abi)
{
    int gt   = blockIdx.x * blockDim.x + threadIdx.x;
    int warp = gt >> 5;
    int lane = gt & 31;
    if (warp >= NB*NN) return;

    const float* xr = Xr + (size_t)warp * NC;
    const float* xi = Xi + (size_t)warp * NC;
    float xr0 = xr[lane], xr1 = xr[lane+32];
    float xi0 = xi[lane], xi1 = xi[lane+32];

    float wsr0 = awr[lane],    wsr1 = awr[lane+32];
    float wdr0 = awr[64+lane], wdr1 = awr[96+lane];
    float wsi0 = awi[lane],    wsi1 = awi[lane+32];
    float wdi0 = awi[64+lane], wdi1 = awi[96+lane];

    float sr = xr0*wsr0 + xr1*wsr1 - xi0*wsi0 - xi1*wsi1;
    float si = xr0*wsi0 + xr1*wsi1 + xi0*wsr0 + xi1*wsr1;
    float dr = xr0*wdr0 + xr1*wdr1 - xi0*wdi0 - xi1*wdi1;
    float di = xr0*wdi0 + xr1*wdi1 + xi0*wdr0 + xi1*wdr1;

    #pragma unroll
    for (int off = 16; off > 0; off >>= 1) {
        sr += __shfl_down_sync(0xFFFFFFFFu, sr, off);
        si += __shfl_down_sync(0xFFFFFFFFu, si, off);
        dr += __shfl_down_sync(0xFFFFFFFFu, dr, off);
        di += __shfl_down_sync(0xFFFFFFFFu, di, off);
    }
    if (lane == 0) {
        g_srcR[warp] = sr + *abr;
        g_srcI[warp] = si + *abi;
        g_dstR[warp] = dr;
        g_dstI[warp] = di;
    }
}

// ---------------------------------------------------------------------------
// Kernel 2: softmax denominator over axis i for each (b, j). Warp per column.
// Stores reciprocal so the main kernel multiplies.
// ---------------------------------------------------------------------------
__global__ void k_denom(const float* __restrict__ par_p, const float* __restrict__ pai_p)
{
    int gt   = blockIdx.x * blockDim.x + threadIdx.x;
    int warp = gt >> 5;
    int lane = gt & 31;
    if (warp >= NB*NN) return;

    int b = warp >> 10;
    float dr = g_dstR[warp], di = g_dstI[warp];
    float par = *par_p, pai = *pai_p;
    const float* sRp = g_srcR + b*NN;
    const float* sIp = g_srcI + b*NN;

    float acc = 0.f;
    #pragma unroll 4
    for (int i = lane; i < NN; i += 32) {
        float sr = sRp[i] + dr;
        float si = sIp[i] + di;
        sr = sr >= 0.f ? sr : par*sr;
        si = si >= 0.f ? si : pai*si;
        float m2  = sr*sr + si*si;
        float mag = m2 > 0.f ? m2 * rsqrtf(m2) : 0.f;
        acc += __expf(mag);
    }
    #pragma unroll
    for (int off = 16; off > 0; off >>= 1)
        acc += __shfl_down_sync(0xFFFFFFFFu, acc, off);
    if (lane == 0) g_rden[warp] = 1.0f / acc;
}

// ---------------------------------------------------------------------------
// Kernel 3 (fused main): per block = (b, 4 consecutive i-rows).
// Phase 1: per thread (j-quad) compute a_r/a_i, stream L rows (5 k × re/im),
//          reduce to SL[r][k] (warp shfl + shared atomics).
// Phase 2: fused einsum 'bkn,bnc,kco->bno' with register-blocked weights.
// ---------------------------------------------------------------------------
__global__ void __launch_bounds__(256, 2)
k_main(const float* __restrict__ L_r, const float* __restrict__ L_i,
       const float* __restrict__ Xr,  const float* __restrict__ Xi,
       const float* __restrict__ wr,  const float* __restrict__ wi,
       const float* __restrict__ par_p, const float* __restrict__ pai_p,
       float* __restrict__ out)
{
    __shared__ float shXr[RPB][NC];
    __shared__ float shXi[RPB][NC];
    __shared__ float shSL[RPB][KP1][2];
    __shared__ float shOut[RPB][NC][2];

    const int t   = threadIdx.x;
    const int blk = blockIdx.x;
    const int b   = blk >> 8;             // 256 blocks per batch (1024/4)
    const int i0  = (blk & 255) * RPB;

    for (int idx = t; idx < RPB*KP1*2; idx += 256) ((float*)shSL)[idx] = 0.f;
    for (int idx = t; idx < RPB*NC*2;  idx += 256) ((float*)shOut)[idx] = 0.f;
    for (int idx = t; idx < RPB*NC;    idx += 256) {
        int r = idx >> 6, c = idx & 63;
        size_t g = ((size_t)(b*NN + i0 + r))*NC + c;
        shXr[r][c] = Xr[g];
        shXi[r][c] = Xi[g];
    }

    const float par = *par_p;
    const float pai = *pai_p;

    // Per-thread column (j) data: j = 4t .. 4t+3
    const float4 dR = ((const float4*)(g_dstR + b*NN))[t];
    const float4 dI = ((const float4*)(g_dstI + b*NN))[t];
    const float4 rd = ((const float4*)(g_rden + b*NN))[t];

    __syncthreads();

    const int lane = t & 31;

    #pragma unroll
    for (int r = 0; r < RPB; r++) {
        const float sR = g_srcR[b*NN + i0 + r];
        const float sI = g_srcI[b*NN + i0 + r];

        float4 ar, ai;
        #define AELEM(comp)                                                   \
        {                                                                     \
            float sr = sR + dR.comp;                                          \
            float si = sI + dI.comp;                                          \
            sr = sr >= 0.f ? sr : par*sr;                                     \
            si = si >= 0.f ? si : pai*si;                                     \
            float m2 = sr*sr + si*si;                                         \
            float rm = m2 > 0.f ? rsqrtf(m2) : 0.f;                           \
            float e  = __expf(m2 * rm);                                       \
            float wq = e * rd.comp * rm;                                      \
            ar.comp = wq * sr;                                                \
            ai.comp = wq * si;                                                \
        }
        AELEM(x) AELEM(y) AELEM(z) AELEM(w)
        #undef AELEM

        float accR[KP1], accI[KP1];
        #pragma unroll
        for (int k = 0; k < KP1; k++) {
            size_t rowoff = ((size_t)((b*KP1 + k)*NN + (i0 + r))) * NN;
            float4 l4r = ((const float4*)(L_r + rowoff))[t];
            float4 l4i = ((const float4*)(L_i + rowoff))[t];
            accR[k] = l4r.x*ar.x + l4r.y*ar.y + l4r.z*ar.z + l4r.w*ar.w
                    - l4i.x*ai.x - l4i.y*ai.y - l4i.z*ai.z - l4i.w*ai.w;
            accI[k] = l4i.x*ar.x + l4i.y*ar.y + l4i.z*ar.z + l4i.w*ar.w
                    + l4r.x*ai.x + l4r.y*ai.y + l4r.z*ai.z + l4r.w*ai.w;
        }
        #pragma unroll
        for (int k = 0; k < KP1; k++) {
            float aR = accR[k], aI = accI[k];
            #pragma unroll
            for (int off = 16; off > 0; off >>= 1) {
                aR += __shfl_down_sync(0xFFFFFFFFu, aR, off);
                aI += __shfl_down_sync(0xFFFFFFFFu, aI, off);
            }
            if (lane == 0) {
                atomicAdd(&shSL[r][k][0], aR);
                atomicAdd(&shSL[r][k][1], aI);
            }
        }
    }
    __syncthreads();

    // ---- Phase 2: fused einsum ----
    // out_r[o] = sum_k SLr[k]*(Xr@wr)[k,o] - SLi[k]*(Xi@wi)[k,o]
    // out_i[o] = sum_k SLi[k]*(Xr@wr)[k,o] + SLr[k]*(Xi@wi)[k,o]
    const int oq = t & 15;   // o-quad: o = 4*oq .. 4*oq+3
    const int cg = t >> 4;   // c-chunk: c = 4*cg .. 4*cg+3

    float4 oR[RPB], oI[RPB];
    #pragma unroll
    for (int r = 0; r < RPB; r++) {
        oR[r] = make_float4(0.f,0.f,0.f,0.f);
        oI[r] = make_float4(0.f,0.f,0.f,0.f);
    }

    #pragma unroll
    for (int k = 0; k < KP1; k++) {
        float4 pr[RPB], pi[RPB];
        #pragma unroll
        for (int r = 0; r < RPB; r++) {
            pr[r] = make_float4(0.f,0.f,0.f,0.f);
            pi[r] = make_float4(0.f,0.f,0.f,0.f);
        }
        #pragma unroll
        for (int cc = 0; cc < 4; cc++) {
            int c = cg*4 + cc;
            float4 w4r = ((const float4*)(wr + ((size_t)k*NC + c)*NC))[oq];
            float4 w4i = ((const float4*)(wi + ((size_t)k*NC + c)*NC))[oq];
            #pragma unroll
            for (int r = 0; r < RPB; r++) {
                float xr = shXr[r][c], xi = shXi[r][c];
                pr[r].x += xr*w4r.x; pr[r].y += xr*w4r.y;
                pr[r].z += xr*w4r.z; pr[r].w += xr*w4r.w;
                pi[r].x += xi*w4i.x; pi[r].y += xi*w4i.y;
                pi[r].z += xi*w4i.z; pi[r].w += xi*w4i.w;
            }
        }
        #pragma unroll
        for (int r = 0; r < RPB; r++) {
            float SR = shSL[r][k][0], SI = shSL[r][k][1];
            oR[r].x += SR*pr[r].x - SI*pi[r].x;
            oR[r].y += SR*pr[r].y - SI*pi[r].y;
            oR[r].z += SR*pr[r].z - SI*pi[r].z;
            oR[r].w += SR*pr[r].w - SI*pi[r].w;
            oI[r].x += SI*pr[r].x + SR*pi[r].x;
            oI[r].y += SI*pr[r].y + SR*pi[r].y;
            oI[r].z += SI*pr[r].z + SR*pi[r].z;
            oI[r].w += SI*pr[r].w + SR*pi[r].w;
        }
    }

    #pragma unroll
    for (int r = 0; r < RPB; r++) {
        atomicAdd(&shOut[r][oq*4+0][0], oR[r].x);
        atomicAdd(&shOut[r][oq*4+1][0], oR[r].y);
        atomicAdd(&shOut[r][oq*4+2][0], oR[r].z);
        atomicAdd(&shOut[r][oq*4+3][0], oR[r].w);
        atomicAdd(&shOut[r][oq*4+0][1], oI[r].x);
        atomicAdd(&shOut[r][oq*4+1][1], oI[r].y);
        atomicAdd(&shOut[r][oq*4+2][1], oI[r].z);
        atomicAdd(&shOut[r][oq*4+3][1], oI[r].w);
    }
    __syncthreads();

    const size_t OUT_HALF = (size_t)NB*NN*NC;
    for (int idx = t; idx < RPB*NC; idx += 256) {
        int r = idx >> 6, o = idx & 63;
        size_t g = ((size_t)(b*NN + i0 + r))*NC + o;
        out[g]            = shOut[r][o][0];
        out[OUT_HALF + g] = shOut[r][o][1];
    }
}

// ---------------------------------------------------------------------------
extern "C" void kernel_launch(void* const* d_in, const int* in_sizes, int n_in,
                              void* d_out, int out_size)
{
    const float* Xr  = (const float*)d_in[0];
    const float* Xi  = (const float*)d_in[1];
    const float* Lr  = (const float*)d_in[2];
    const float* Li  = (const float*)d_in[3];
    const float* wr  = (const float*)d_in[4];
    const float* wi  = (const float*)d_in[5];
    const float* awr = (const float*)d_in[6];
    const float* awi = (const float*)d_in[7];
    const float* abr = (const float*)d_in[8];
    const float* abi = (const float*)d_in[9];
    const float* par = (const float*)d_in[10];
    const float* pai = (const float*)d_in[11];
    float* out = (float*)d_out;

    k_src<<<NB*NN/8, 256>>>(Xr, Xi, awr, awi, abr, abi);
    k_denom<<<NB*NN/8, 256>>>(par, pai);
    k_main<<<NB*NN/RPB, 256>>>(Lr, Li, Xr, Xi, wr, wi, par, pai, out);
}

// round 3
// speedup vs baseline: 1.3909x; 1.3909x over previous
#include <cuda_runtime.h>
#include <cuda_bf16.h>

#define NB   8
#define NN   1024
#define NC   64
#define OC   64
#define KP1  5
#define RPB  4
#define ROWS (NB*NN)      // 8192
#define YSTR (KP1*OC)     // 320

// Scratch (static device globals; no allocations allowed)
__device__ __align__(16) float g_srcR[ROWS];
__device__ __align__(16) float g_srcI[ROWS];
__device__ __align__(16) float g_dstR[ROWS];
__device__ __align__(16) float g_dstI[ROWS];
__device__ __align__(16) float g_rden[ROWS];
__device__ __align__(16) float g_Yrr[ROWS*YSTR];   // Xr @ wr  per k
__device__ __align__(16) float g_Yii[ROWS*YSTR];   // Xi @ wi  per k

// ---- packed fp32x2 helpers (sm_103a FFMA2) --------------------------------
typedef unsigned long long u64t;
__device__ __forceinline__ u64t pk2(float lo, float hi) {
    u64t d; asm("mov.b64 %0,{%1,%2};" : "=l"(d) : "f"(lo), "f"(hi)); return d;
}
__device__ __forceinline__ void upk2(u64t v, float& lo, float& hi) {
    asm("mov.b64 {%0,%1},%2;" : "=f"(lo), "=f"(hi) : "l"(v));
}
__device__ __forceinline__ u64t fma2(u64t a, u64t b, u64t c) {
    u64t d; asm("fma.rn.f32x2 %0,%1,%2,%3;" : "=l"(d) : "l"(a), "l"(b), "l"(c)); return d;
}

// ---------------------------------------------------------------------------
// Kernel 1: per-row complex projections. One warp per (b,n) row.
// ---------------------------------------------------------------------------
__global__ void k_src(const float* __restrict__ Xr, const float* __restrict__ Xi,
                      const float* __restrict__ awr, const float* __restrict__ awi,
                      const float* __restrict__ abr, const float* __restrict__ abi)
{
    int gt   = blockIdx.x * blockDim.x + threadIdx.x;
    int warp = gt >> 5;
    int lane = gt & 31;
    if (warp >= ROWS) return;

    const float* xr = Xr + (size_t)warp * NC;
    const float* xi = Xi + (size_t)warp * NC;
    float xr0 = xr[lane], xr1 = xr[lane+32];
    float xi0 = xi[lane], xi1 = xi[lane+32];

    float wsr0 = awr[lane],    wsr1 = awr[lane+32];
    float wdr0 = awr[64+lane], wdr1 = awr[96+lane];
    float wsi0 = awi[lane],    wsi1 = awi[lane+32];
    float wdi0 = awi[64+lane], wdi1 = awi[96+lane];

    float sr = xr0*wsr0 + xr1*wsr1 - xi0*wsi0 - xi1*wsi1;
    float si = xr0*wsi0 + xr1*wsi1 + xi0*wsr0 + xi1*wsr1;
    float dr = xr0*wdr0 + xr1*wdr1 - xi0*wdi0 - xi1*wdi1;
    float di = xr0*wdi0 + xr1*wdi1 + xi0*wdr0 + xi1*wdr1;

    #pragma unroll
    for (int off = 16; off > 0; off >>= 1) {
        sr += __shfl_down_sync(0xFFFFFFFFu, sr, off);
        si += __shfl_down_sync(0xFFFFFFFFu, si, off);
        dr += __shfl_down_sync(0xFFFFFFFFu, dr, off);
        di += __shfl_down_sync(0xFFFFFFFFu, di, off);
    }
    if (lane == 0) {
        g_srcR[warp] = sr + *abr;
        g_srcI[warp] = si + *abi;
        g_dstR[warp] = dr;
        g_dstI[warp] = di;
    }
}

// ---------------------------------------------------------------------------
// Kernel 2: softmax denominators (axis i per (b,j)); stores reciprocal.
// ---------------------------------------------------------------------------
__global__ void k_denom(const float* __restrict__ par_p, const float* __restrict__ pai_p)
{
    int gt   = blockIdx.x * blockDim.x + threadIdx.x;
    int warp = gt >> 5;
    int lane = gt & 31;
    if (warp >= ROWS) return;

    int b = warp >> 10;
    float dr = g_dstR[warp], di = g_dstI[warp];
    float par = *par_p, pai = *pai_p;
    const float* sRp = g_srcR + b*NN;
    const float* sIp = g_srcI + b*NN;

    float acc = 0.f;
    #pragma unroll 4
    for (int i = lane; i < NN; i += 32) {
        float sr = sRp[i] + dr;
        float si = sIp[i] + di;
        sr = sr >= 0.f ? sr : par*sr;
        si = si >= 0.f ? si : pai*si;
        float m2  = sr*sr + si*si;
        float mag = m2 > 0.f ? m2 * rsqrtf(m2) : 0.f;
        acc += __expf(mag);
    }
    #pragma unroll
    for (int off = 16; off > 0; off >>= 1)
        acc += __shfl_down_sync(0xFFFFFFFFu, acc, off);
    if (lane == 0) g_rden[warp] = 1.0f / acc;
}

// ---------------------------------------------------------------------------
// Kernel 3: Y[n,k,o] = (X @ w[k]) for both (Xr,wr) and (Xi,wi).
// 10 independent 8192x64x64 fp32 GEMMs; f32x2 on o-pairs.
// grid = (128 n-tiles, 5 k, 2 parts), 256 threads.
// ---------------------------------------------------------------------------
__global__ void __launch_bounds__(256)
k_gemm(const float* __restrict__ Xr, const float* __restrict__ Xi,
       const float* __restrict__ wr, const float* __restrict__ wi)
{
    __shared__ __align__(16) float As[64][64];   // [row][c]
    __shared__ __align__(16) float Ws[64][64];   // [c][o]

    const int t    = threadIdx.x;
    const int n0   = blockIdx.x * 64;
    const int k    = blockIdx.y;
    const int part = blockIdx.z;

    const float* A = part ? Xi : Xr;
    const float* W = (part ? wi : wr) + (size_t)k * NC * OC;
    float*       Y = part ? g_Yii : g_Yrr;

    for (int idx = t; idx < 64*64; idx += 256) {
        int r = idx >> 6, c = idx & 63;
        As[r][c] = A[(size_t)(n0 + r) * NC + c];
        ((float*)Ws)[idx] = W[idx];
    }
    __syncthreads();

    const int oq = t & 15;   // o-quad
    const int rg = t >> 4;   // row group of 4

    u64t acc[4][2];
    #pragma unroll
    for (int rr = 0; rr < 4; rr++) { acc[rr][0] = 0ULL; acc[rr][1] = 0ULL; }

    #pragma unroll 8
    for (int c = 0; c < 64; c++) {
        ulonglong2 wv = *(const ulonglong2*)&Ws[c][oq*4];
        #pragma unroll
        for (int rr = 0; rr < 4; rr++) {
            float a  = As[rg*4 + rr][c];
            u64t  a2 = pk2(a, a);
            acc[rr][0] = fma2(a2, wv.x, acc[rr][0]);
            acc[rr][1] = fma2(a2, wv.y, acc[rr][1]);
        }
    }

    #pragma unroll
    for (int rr = 0; rr < 4; rr++) {
        float4 v;
        upk2(acc[rr][0], v.x, v.y);
        upk2(acc[rr][1], v.z, v.w);
        *(float4*)&Y[(size_t)(n0 + rg*4 + rr) * YSTR + k*OC + oq*4] = v;
    }
}

// ---------------------------------------------------------------------------
// Kernel 4 (main): per block = (b, 4 rows). Stream L (5k x re/im x 4KB rows),
// weighted reduction with f32x2, then tiny Y-combine epilogue.
// ---------------------------------------------------------------------------
__global__ void __launch_bounds__(256, 3)
k_main(const float* __restrict__ L_r, const float* __restrict__ L_i,
       const float* __restrict__ par_p, const float* __restrict__ pai_p,
       float* __restrict__ out)
{
    __shared__ float shSL[RPB][KP1][2];

    const int t   = threadIdx.x;
    const int blk = blockIdx.x;
    const int b   = blk >> 8;
    const int i0  = (blk & 255) * RPB;

    if (t < RPB*KP1*2) ((float*)shSL)[t] = 0.f;

    const float par = *par_p;
    const float pai = *pai_p;

    // per-thread column data: j = 4t .. 4t+3
    const float4 dR = ((const float4*)(g_dstR + b*NN))[t];
    const float4 dI = ((const float4*)(g_dstI + b*NN))[t];
    const float4 rd = ((const float4*)(g_rden + b*NN))[t];
    __syncthreads();

    const int lane = t & 31;

    #pragma unroll
    for (int r = 0; r < RPB; r++) {
        const float sR = g_srcR[b*NN + i0 + r];
        const float sI = g_srcI[b*NN + i0 + r];

        float arr[4], aii[4];
        const float drv[4] = {dR.x, dR.y, dR.z, dR.w};
        const float div[4] = {dI.x, dI.y, dI.z, dI.w};
        const float rdv[4] = {rd.x, rd.y, rd.z, rd.w};
        #pragma unroll
        for (int j = 0; j < 4; j++) {
            float sr = sR + drv[j];
            float si = sI + div[j];
            sr = sr >= 0.f ? sr : par*sr;
            si = si >= 0.f ? si : pai*si;
            float m2 = sr*sr + si*si;
            float rm = m2 > 0.f ? rsqrtf(m2) : 0.f;
            float e  = __expf(m2 * rm);
            float wq = e * rdv[j] * rm;
            arr[j] = wq * sr;
            aii[j] = wq * si;
        }
        u64t ar01 = pk2(arr[0], arr[1]), ar23 = pk2(arr[2], arr[3]);
        u64t ai01 = pk2(aii[0], aii[1]), ai23 = pk2(aii[2], aii[3]);
        u64t nai01 = pk2(-aii[0], -aii[1]), nai23 = pk2(-aii[2], -aii[3]);

        u64t aR2[KP1], aI2[KP1];
        #pragma unroll
        for (int k = 0; k < KP1; k++) { aR2[k] = 0ULL; aI2[k] = 0ULL; }

        #pragma unroll
        for (int k = 0; k < KP1; k++) {
            size_t rowoff = ((size_t)((b*KP1 + k)*NN + (i0 + r))) * NN;
            const ulonglong2 lr = ((const ulonglong2*)(L_r + rowoff))[t];
            const ulonglong2 li = ((const ulonglong2*)(L_i + rowoff))[t];
            aR2[k] = fma2(lr.x, ar01,  aR2[k]);
            aR2[k] = fma2(lr.y, ar23,  aR2[k]);
            aR2[k] = fma2(li.x, nai01, aR2[k]);
            aR2[k] = fma2(li.y, nai23, aR2[k]);
            aI2[k] = fma2(li.x, ar01,  aI2[k]);
            aI2[k] = fma2(li.y, ar23,  aI2[k]);
            aI2[k] = fma2(lr.x, ai01,  aI2[k]);
            aI2[k] = fma2(lr.y, ai23,  aI2[k]);
        }

        #pragma unroll
        for (int k = 0; k < KP1; k++) {
            float lo, hi, aR, aI;
            upk2(aR2[k], lo, hi); aR = lo + hi;
            upk2(aI2[k], lo, hi); aI = lo + hi;
            #pragma unroll
            for (int off = 16; off > 0; off >>= 1) {
                aR += __shfl_down_sync(0xFFFFFFFFu, aR, off);
                aI += __shfl_down_sync(0xFFFFFFFFu, aI, off);
            }
            if (lane == 0) {
                atomicAdd(&shSL[r][k][0], aR);
                atomicAdd(&shSL[r][k][1], aI);
            }
        }
    }
    __syncthreads();

    // ---- epilogue: out = SL (x) Y combine. thread = (r, o) ----
    {
        const int r = t >> 6;
        const int o = t & 63;
        const int row = b*NN + i0 + r;
        const float* yrr = g_Yrr + (size_t)row * YSTR + o;
        const float* yii = g_Yii + (size_t)row * YSTR + o;
        float or_ = 0.f, oi_ = 0.f;
        #pragma unroll
        for (int k = 0; k < KP1; k++) {
            float SR = shSL[r][k][0], SI = shSL[r][k][1];
            float yr = yrr[k*OC], yi = yii[k*OC];
            or_ += SR*yr - SI*yi;
            oi_ += SI*yr + SR*yi;
        }
        const size_t OUT_HALF = (size_t)ROWS * OC;
        size_t g = (size_t)row * OC + o;
        out[g]            = or_;
        out[OUT_HALF + g] = oi_;
    }
}

// ---------------------------------------------------------------------------
extern "C" void kernel_launch(void* const* d_in, const int* in_sizes, int n_in,
                              void* d_out, int out_size)
{
    const float* Xr  = (const float*)d_in[0];
    const float* Xi  = (const float*)d_in[1];
    const float* Lr  = (const float*)d_in[2];
    const float* Li  = (const float*)d_in[3];
    const float* wr  = (const float*)d_in[4];
    const float* wi  = (const float*)d_in[5];
    const float* awr = (const float*)d_in[6];
    const float* awi = (const float*)d_in[7];
    const float* abr = (const float*)d_in[8];
    const float* abi = (const float*)d_in[9];
    const float* par = (const float*)d_in[10];
    const float* pai = (const float*)d_in[11];
    float* out = (float*)d_out;

    k_src  <<<ROWS/8, 256>>>(Xr, Xi, awr, awi, abr, abi);
    k_denom<<<ROWS/8, 256>>>(par, pai);
    k_gemm <<<dim3(ROWS/64, KP1, 2), 256>>>(Xr, Xi, wr, wi);
    k_main <<<ROWS/RPB, 256>>>(Lr, Li, par, pai, out);
}